// round 12
// baseline (speedup 1.0000x reference)
#include <cuda_runtime.h>
#include <cuda_bf16.h>
#include <cstddef>

#define NN 50000
#define EE 800000
#define NF 256
#define HH 128
#define LL 3
#define NEG_SLOPE 0.01f
#define NBLK 196   // ceil(NN/256)

// ---------------- scratch (no allocations allowed) ----------------
__device__ float         g_cur [(size_t)NN * HH];   // hidden h ping
__device__ float         g_cur2[(size_t)NN * HH];   // hidden h pong
__device__ __nv_bfloat16 g_h0b [(size_t)NN * HH];   // projection output (bf16)
__device__ __nv_bfloat16 g_msgb [(size_t)NN * HH];  // h*invdeg messages ping
__device__ __nv_bfloat16 g_msgb2[(size_t)NN * HH];  // h*invdeg messages pong
__device__ float g_invdeg[NN];
__device__ float g_colsum[HH * (LL + 1)];
__device__ int   g_cnt[NN];
__device__ int   g_rank[EE];
__device__ int   g_rowptr[NN + 1];
__device__ int   g_col[EE];                // src node per dst-sorted edge
__device__ int   g_bsum[NBLK];
__device__ int   g_boff[NBLK];

// ---------------- helpers ----------------
__device__ __forceinline__ unsigned f2tf32(float x) {
    unsigned u;
    asm("cvt.rna.tf32.f32 %0, %1;" : "=r"(u) : "f"(x));
    return u;
}

__device__ __forceinline__ unsigned packbf2(float lo, float hi) {
    __nv_bfloat162 b = __floats2bfloat162_rn(lo, hi);
    return *reinterpret_cast<unsigned*>(&b);
}

__device__ __forceinline__ void mma_tf32(float* d, const unsigned* a, const unsigned* b) {
    asm volatile(
        "mma.sync.aligned.m16n8k8.row.col.f32.tf32.tf32.f32 "
        "{%0,%1,%2,%3}, {%4,%5,%6,%7}, {%8,%9}, {%0,%1,%2,%3};\n"
        : "+f"(d[0]), "+f"(d[1]), "+f"(d[2]), "+f"(d[3])
        : "r"(a[0]), "r"(a[1]), "r"(a[2]), "r"(a[3]), "r"(b[0]), "r"(b[1]));
}

__device__ __forceinline__ void acc_bf16row(float4& acc, const __nv_bfloat16* p) {
    uint2 r = *reinterpret_cast<const uint2*>(p);
    __nv_bfloat162 b0 = *reinterpret_cast<const __nv_bfloat162*>(&r.x);
    __nv_bfloat162 b1 = *reinterpret_cast<const __nv_bfloat162*>(&r.y);
    float2 f0 = __bfloat1622float2(b0);
    float2 f1 = __bfloat1622float2(b1);
    acc.x += f0.x; acc.y += f0.y; acc.z += f1.x; acc.w += f1.y;
}

// ---------------- colsum zero (main stream, before fork) ----------------
__global__ void zero_cs_kernel(float* __restrict__ cs) {
    int i = blockIdx.x * blockDim.x + threadIdx.x;
    if (i < HH * (LL + 1)) cs[i] = 0.f;
}

// ---------------- init (s2): counters + invdeg ----------------
__global__ void init_kernel(const float* __restrict__ degree, float* __restrict__ invdeg,
                            int* __restrict__ cnt) {
    int i = blockIdx.x * blockDim.x + threadIdx.x;
    if (i < NN) {
        invdeg[i] = 1.0f / degree[i];
        cnt[i] = 0;
    }
}

// ---------------- CSR build ----------------
__global__ void hist_kernel(const int* __restrict__ dst, int* __restrict__ cnt,
                            int* __restrict__ rank) {
    int e = blockIdx.x * blockDim.x + threadIdx.x;
    if (e < EE) rank[e] = atomicAdd(&cnt[dst[e]], 1);
}

__global__ void scan1_kernel(const int* __restrict__ cnt, int* __restrict__ rowptr,
                             int* __restrict__ bsum) {
    __shared__ int ws[8];
    int tid = threadIdx.x, lane = tid & 31, wid = tid >> 5;
    int i = blockIdx.x * 256 + tid;
    int v = (i < NN) ? cnt[i] : 0;
    int x = v;
#pragma unroll
    for (int off = 1; off < 32; off <<= 1) {
        int y = __shfl_up_sync(0xffffffffu, x, off);
        if (lane >= off) x += y;
    }
    if (lane == 31) ws[wid] = x;
    __syncthreads();
    if (wid == 0 && lane < 8) {
        int s = ws[lane];
#pragma unroll
        for (int off = 1; off < 8; off <<= 1) {
            int y = __shfl_up_sync(0x000000ffu, s, off);
            if (lane >= off) s += y;
        }
        ws[lane] = s;
    }
    __syncthreads();
    int woff = wid ? ws[wid - 1] : 0;
    if (i < NN) rowptr[i] = woff + x - v;
    if (tid == 255) bsum[blockIdx.x] = woff + x;
}

__global__ void scan2_kernel(const int* __restrict__ bsum, int* __restrict__ boff,
                             int* __restrict__ rowptr) {
    __shared__ int ws[8];
    int tid = threadIdx.x, lane = tid & 31, wid = tid >> 5;
    int v = (tid < NBLK) ? bsum[tid] : 0;
    int x = v;
#pragma unroll
    for (int off = 1; off < 32; off <<= 1) {
        int y = __shfl_up_sync(0xffffffffu, x, off);
        if (lane >= off) x += y;
    }
    if (lane == 31) ws[wid] = x;
    __syncthreads();
    if (wid == 0 && lane < 8) {
        int s = ws[lane];
#pragma unroll
        for (int off = 1; off < 8; off <<= 1) {
            int y = __shfl_up_sync(0x000000ffu, s, off);
            if (lane >= off) s += y;
        }
        ws[lane] = s;
    }
    __syncthreads();
    int woff = wid ? ws[wid - 1] : 0;
    if (tid < NBLK) boff[tid] = woff + x - v;
    if (tid == 255) rowptr[NN] = woff + x;
}

__global__ void scan3_kernel(int* __restrict__ rowptr, const int* __restrict__ boff) {
    int i = blockIdx.x * 256 + threadIdx.x;
    if (i < NN) rowptr[i] += boff[blockIdx.x];
}

__global__ void fill_kernel(const int* __restrict__ src, const int* __restrict__ dst,
                            const int* __restrict__ rowptr, const int* __restrict__ rank,
                            int* __restrict__ col) {
    int e = blockIdx.x * blockDim.x + threadIdx.x;
    if (e >= EE) return;
    col[rowptr[dst[e]] + rank[e]] = src[e];
}

// ---------------- fusion gather (standalone, as R9) ----------------
// cur[v] = sum_{u->v} h0b[u]; msgb[v] = bf16(cur[v]*invdeg[v]).
__global__ __launch_bounds__(256)
void fusion_gather_kernel(const __nv_bfloat16* __restrict__ msg,
                          float* __restrict__ out, __nv_bfloat16* __restrict__ outb,
                          const float* __restrict__ invdeg,
                          const int* __restrict__ rowptr, const int* __restrict__ col) {
    int node = (blockIdx.x * blockDim.x + threadIdx.x) >> 5;
    int lane = threadIdx.x & 31;
    if (node >= NN) return;
    int s0 = __ldg(rowptr + node), s1 = __ldg(rowptr + node + 1);

    float4 acc = make_float4(0.f, 0.f, 0.f, 0.f);
    const __nv_bfloat16* mbase = msg + lane * 4;
    int e = s0;
    for (; e + 3 < s1; e += 4) {
        int u0 = __ldg(col + e),     u1 = __ldg(col + e + 1);
        int u2 = __ldg(col + e + 2), u3 = __ldg(col + e + 3);
        acc_bf16row(acc, mbase + (size_t)u0 * HH);
        acc_bf16row(acc, mbase + (size_t)u1 * HH);
        acc_bf16row(acc, mbase + (size_t)u2 * HH);
        acc_bf16row(acc, mbase + (size_t)u3 * HH);
    }
    for (; e < s1; e++) {
        int u0 = __ldg(col + e);
        acc_bf16row(acc, mbase + (size_t)u0 * HH);
    }

    *reinterpret_cast<float4*>(out + (size_t)node * HH + lane * 4) = acc;
    float iv = __ldg(invdeg + node);
    uint2 p;
    p.x = packbf2(acc.x * iv, acc.y * iv);
    p.y = packbf2(acc.z * iv, acc.w * iv);
    *reinterpret_cast<uint2*>(outb + (size_t)node * HH + lane * 4) = p;
}

// ---------------- projection GEMM (tf32, 256 thr): h0b = bf16(A@W+b) ----------------
__global__ __launch_bounds__(256, 2)
void gemm_proj(const float* __restrict__ A, const float* __restrict__ W,
               const float* __restrict__ bias, __nv_bfloat16* __restrict__ Cb,
               float* __restrict__ colsum) {
    __shared__ unsigned As[128][36];
    __shared__ unsigned Ws[32][132];
    __shared__ float colsm[HH];

    const int tid = threadIdx.x;
    const int warp = tid >> 5, lane = tid & 31;
    const int wm = warp & 3, wn = warp >> 2;
    const int g = lane >> 2, t = lane & 3;
    const int row0 = blockIdx.x * 128;

    float acc[2][8][4];
#pragma unroll
    for (int mt = 0; mt < 2; mt++)
#pragma unroll
        for (int nt = 0; nt < 8; nt++)
#pragma unroll
            for (int r = 0; r < 4; r++) acc[mt][nt][r] = 0.f;

    if (tid < HH) colsm[tid] = 0.f;

    for (int k0 = 0; k0 < NF; k0 += 32) {
#pragma unroll
        for (int i = 0; i < 4; i++) {
            int idx = tid + i * 256;
            int r = idx >> 3, q = idx & 7;
            float4 v = make_float4(0.f, 0.f, 0.f, 0.f);
            if (row0 + r < NN)
                v = *reinterpret_cast<const float4*>(A + (size_t)(row0 + r) * NF + k0 + q * 4);
            unsigned* p = &As[r][q * 4];
            p[0] = f2tf32(v.x); p[1] = f2tf32(v.y); p[2] = f2tf32(v.z); p[3] = f2tf32(v.w);
        }
#pragma unroll
        for (int i = 0; i < 4; i++) {
            int idx = tid + i * 256;
            int kk = idx >> 5, n4 = idx & 31;
            float4 w = *reinterpret_cast<const float4*>(W + (size_t)(k0 + kk) * HH + n4 * 4);
            unsigned* p = &Ws[kk][n4 * 4];
            p[0] = f2tf32(w.x); p[1] = f2tf32(w.y); p[2] = f2tf32(w.z); p[3] = f2tf32(w.w);
        }
        __syncthreads();

#pragma unroll
        for (int k8 = 0; k8 < 4; k8++) {
            const int kk = k8 * 8;
            unsigned a[2][4], b[8][2];
#pragma unroll
            for (int mt = 0; mt < 2; mt++) {
                int r = wm * 32 + mt * 16;
                a[mt][0] = As[r + g][kk + t];
                a[mt][1] = As[r + g + 8][kk + t];
                a[mt][2] = As[r + g][kk + t + 4];
                a[mt][3] = As[r + g + 8][kk + t + 4];
            }
#pragma unroll
            for (int nt = 0; nt < 8; nt++) {
                int n = wn * 64 + nt * 8;
                b[nt][0] = Ws[kk + t][n + g];
                b[nt][1] = Ws[kk + t + 4][n + g];
            }
#pragma unroll
            for (int mt = 0; mt < 2; mt++)
#pragma unroll
                for (int nt = 0; nt < 8; nt++)
                    mma_tf32(acc[mt][nt], a[mt], b[nt]);
        }
        __syncthreads();
    }

    float csum[8][2];
#pragma unroll
    for (int nt = 0; nt < 8; nt++) { csum[nt][0] = 0.f; csum[nt][1] = 0.f; }

#pragma unroll
    for (int mt = 0; mt < 2; mt++) {
        int rr[2];
        rr[0] = row0 + wm * 32 + mt * 16 + g;
        rr[1] = rr[0] + 8;
#pragma unroll
        for (int half = 0; half < 2; half++) {
            int r = rr[half];
            if (r >= NN) continue;
#pragma unroll
            for (int nt = 0; nt < 8; nt++) {
                int col = wn * 64 + nt * 8 + 2 * t;
                float b0 = __ldg(bias + col), b1 = __ldg(bias + col + 1);
                float x0 = acc[mt][nt][half * 2 + 0] + b0;
                float x1 = acc[mt][nt][half * 2 + 1] + b1;
                csum[nt][0] += x0; csum[nt][1] += x1;
                *reinterpret_cast<unsigned*>(Cb + (size_t)r * HH + col) = packbf2(x0, x1);
            }
        }
    }

    __syncthreads();
#pragma unroll
    for (int nt = 0; nt < 8; nt++) {
#pragma unroll
        for (int c = 0; c < 2; c++) {
            float s = csum[nt][c];
            s += __shfl_xor_sync(0xffffffffu, s, 4);
            s += __shfl_xor_sync(0xffffffffu, s, 8);
            s += __shfl_xor_sync(0xffffffffu, s, 16);
            if (g == 0) atomicAdd(&colsm[wn * 64 + nt * 8 + 2 * t + c], s);
        }
    }
    __syncthreads();
    if (tid < HH) atomicAdd(&colsum[tid], colsm[tid]);
}

// ---------------- fused layer: gather (into smem A-tile) + tf32 GEMM ----------------
// Phase 1: 16 warps gather 8 nodes each: agg = cur_in[v] + sum msgb_in[u] -> As (tf32).
// Phase 2: 32x32 warp-tile GEMM over resident K=128; epilogue bias+leaky+colsum,
//          write cur_out fp32 + msgb_out bf16 (unless LAST: colsum only).
#define FUSED_SMEM_BYTES ((128 * 132 + 32 * 132) * 4 + HH * 4)

template <bool LAST>
__global__ __launch_bounds__(512, 2)
void fused_layer(const float* __restrict__ cur_in, const __nv_bfloat16* __restrict__ msgb_in,
                 const float* __restrict__ W, const float* __restrict__ bias,
                 float* __restrict__ cur_out, __nv_bfloat16* __restrict__ msgb_out,
                 const float* __restrict__ invdeg,
                 const int* __restrict__ rowptr, const int* __restrict__ colidx,
                 float* __restrict__ colsum, int cs_off) {
    extern __shared__ unsigned smem[];
    unsigned (*As)[132] = reinterpret_cast<unsigned(*)[132]>(smem);            // [128][132]
    unsigned (*Ws)[132] = reinterpret_cast<unsigned(*)[132]>(smem + 128 * 132); // [32][132]
    float* colsm = reinterpret_cast<float*>(smem + 128 * 132 + 32 * 132);      // [128]

    const int tid = threadIdx.x;
    const int warp = tid >> 5, lane = tid & 31;
    const int row0 = blockIdx.x * 128;

    if (tid < HH) colsm[tid] = 0.f;

    // ---- phase 1: gather into As ----
    const __nv_bfloat16* mbase = msgb_in + lane * 4;
#pragma unroll 1
    for (int i = 0; i < 8; i++) {
        int r = warp * 8 + i;
        int node = row0 + r;
        float4 acc = make_float4(0.f, 0.f, 0.f, 0.f);
        if (node < NN) {
            acc = *reinterpret_cast<const float4*>(cur_in + (size_t)node * HH + lane * 4);
            int s0 = __ldg(rowptr + node), s1 = __ldg(rowptr + node + 1);
            int e = s0;
            for (; e + 3 < s1; e += 4) {
                int u0 = __ldg(colidx + e),     u1 = __ldg(colidx + e + 1);
                int u2 = __ldg(colidx + e + 2), u3 = __ldg(colidx + e + 3);
                acc_bf16row(acc, mbase + (size_t)u0 * HH);
                acc_bf16row(acc, mbase + (size_t)u1 * HH);
                acc_bf16row(acc, mbase + (size_t)u2 * HH);
                acc_bf16row(acc, mbase + (size_t)u3 * HH);
            }
            for (; e < s1; e++) {
                int u0 = __ldg(colidx + e);
                acc_bf16row(acc, mbase + (size_t)u0 * HH);
            }
        }
        unsigned* p = &As[r][lane * 4];
        p[0] = f2tf32(acc.x); p[1] = f2tf32(acc.y);
        p[2] = f2tf32(acc.z); p[3] = f2tf32(acc.w);
    }
    __syncthreads();

    // ---- phase 2: GEMM (warp tile 32m x 32n) ----
    const int wm = warp & 3, wn = warp >> 2;
    const int g = lane >> 2, t = lane & 3;

    float acc[2][4][4];
#pragma unroll
    for (int mt = 0; mt < 2; mt++)
#pragma unroll
        for (int nt = 0; nt < 4; nt++)
#pragma unroll
            for (int r = 0; r < 4; r++) acc[mt][nt][r] = 0.f;

    for (int k0 = 0; k0 < HH; k0 += 32) {
        // W tile 32x128: 1024 float4, 2 per thread
#pragma unroll
        for (int i = 0; i < 2; i++) {
            int idx = tid + i * 512;
            int kk = idx >> 5, n4 = idx & 31;
            float4 w = *reinterpret_cast<const float4*>(W + (size_t)(k0 + kk) * HH + n4 * 4);
            unsigned* p = &Ws[kk][n4 * 4];
            p[0] = f2tf32(w.x); p[1] = f2tf32(w.y); p[2] = f2tf32(w.z); p[3] = f2tf32(w.w);
        }
        __syncthreads();

#pragma unroll
        for (int k8 = 0; k8 < 4; k8++) {
            const int kk = k8 * 8;
            unsigned a[2][4], b[4][2];
#pragma unroll
            for (int mt = 0; mt < 2; mt++) {
                int r = wm * 32 + mt * 16;
                a[mt][0] = As[r + g][k0 + kk + t];
                a[mt][1] = As[r + g + 8][k0 + kk + t];
                a[mt][2] = As[r + g][k0 + kk + t + 4];
                a[mt][3] = As[r + g + 8][k0 + kk + t + 4];
            }
#pragma unroll
            for (int nt = 0; nt < 4; nt++) {
                int n = wn * 32 + nt * 8;
                b[nt][0] = Ws[kk + t][n + g];
                b[nt][1] = Ws[kk + t + 4][n + g];
            }
#pragma unroll
            for (int mt = 0; mt < 2; mt++)
#pragma unroll
                for (int nt = 0; nt < 4; nt++)
                    mma_tf32(acc[mt][nt], a[mt], b[nt]);
        }
        __syncthreads();
    }

    // ---- epilogue ----
    float csum[4][2];
#pragma unroll
    for (int nt = 0; nt < 4; nt++) { csum[nt][0] = 0.f; csum[nt][1] = 0.f; }

#pragma unroll
    for (int mt = 0; mt < 2; mt++) {
        int rr[2];
        rr[0] = row0 + wm * 32 + mt * 16 + g;
        rr[1] = rr[0] + 8;
#pragma unroll
        for (int half = 0; half < 2; half++) {
            int r = rr[half];
            if (r >= NN) continue;
            float iv = LAST ? 1.0f : __ldg(invdeg + r);
#pragma unroll
            for (int nt = 0; nt < 4; nt++) {
                int col = wn * 32 + nt * 8 + 2 * t;
                float b0 = __ldg(bias + col), b1 = __ldg(bias + col + 1);
                float x0 = acc[mt][nt][half * 2 + 0] + b0;
                float x1 = acc[mt][nt][half * 2 + 1] + b1;
                x0 = (x0 >= 0.f) ? x0 : NEG_SLOPE * x0;
                x1 = (x1 >= 0.f) ? x1 : NEG_SLOPE * x1;
                csum[nt][0] += x0; csum[nt][1] += x1;
                if (!LAST) {
                    *reinterpret_cast<float2*>(cur_out + (size_t)r * HH + col) =
                        make_float2(x0, x1);
                    *reinterpret_cast<unsigned*>(msgb_out + (size_t)r * HH + col) =
                        packbf2(x0 * iv, x1 * iv);
                }
            }
        }
    }

    __syncthreads();
#pragma unroll
    for (int nt = 0; nt < 4; nt++) {
#pragma unroll
        for (int c = 0; c < 2; c++) {
            float s = csum[nt][c];
            s += __shfl_xor_sync(0xffffffffu, s, 4);
            s += __shfl_xor_sync(0xffffffffu, s, 8);
            s += __shfl_xor_sync(0xffffffffu, s, 16);
            if (g == 0) atomicAdd(&colsm[wn * 32 + nt * 8 + 2 * t + c], s);
        }
    }
    __syncthreads();
    if (tid < HH) atomicAdd(&colsum[cs_off + tid], colsm[tid]);
}

// ---------------- final ----------------
__global__ void final_kernel(const float* __restrict__ colsum,
                             const float* __restrict__ Wpred, const float* __restrict__ bpred,
                             const float* __restrict__ Wcls, const float* __restrict__ bcls,
                             float* __restrict__ out) {
    __shared__ float cm[HH * (LL + 1)];
    __shared__ float gsh[HH];
    int tid = threadIdx.x;  // 128 threads
    for (int t = tid; t < HH * (LL + 1); t += 128) cm[t] = colsum[t] * (1.0f / (float)NN);
    __syncthreads();
    float g = bpred[tid];
    for (int k = 0; k < HH * (LL + 1); k++) g += cm[k] * Wpred[(size_t)k * HH + tid];
    gsh[tid] = g;
    __syncthreads();
    if (tid == 0) {
        float l0 = bcls[0], l1 = bcls[1];
        for (int j = 0; j < HH; j++) {
            l0 += gsh[j] * Wcls[j * 2 + 0];
            l1 += gsh[j] * Wcls[j * 2 + 1];
        }
        float m = fmaxf(l0, l1);
        float e0 = expf(l0 - m), e1 = expf(l1 - m);
        float inv = 1.0f / (e0 + e1);
        out[0] = e0 * inv;
        out[1] = e1 * inv;
    }
}

// ---------------- launch ----------------
extern "C" void kernel_launch(void* const* d_in, const int* in_sizes, int n_in,
                              void* d_out, int out_size) {
    const float* node_feat = (const float*)d_in[0];
    const float* degree    = (const float*)d_in[3];
    const float* Wn        = (const float*)d_in[4];
    const float* bn        = (const float*)d_in[5];
    const float* Wgcn      = (const float*)d_in[8];
    const float* bgcn      = (const float*)d_in[9];
    const float* Wpred     = (const float*)d_in[10];
    const float* bpred     = (const float*)d_in[11];
    const float* Wcls      = (const float*)d_in[12];
    const float* bcls      = (const float*)d_in[13];
    const int*   src       = (const int*)d_in[14];
    const int*   dst       = (const int*)d_in[15];
    float* out = (float*)d_out;

    float *p_cur, *p_cur2, *p_inv, *p_cs;
    __nv_bfloat16 *p_h0b, *p_msgb, *p_msgb2;
    int *p_cnt, *p_rank, *p_rp, *p_col, *p_bsum, *p_boff;
    cudaGetSymbolAddress((void**)&p_cur,   g_cur);
    cudaGetSymbolAddress((void**)&p_cur2,  g_cur2);
    cudaGetSymbolAddress((void**)&p_h0b,   g_h0b);
    cudaGetSymbolAddress((void**)&p_msgb,  g_msgb);
    cudaGetSymbolAddress((void**)&p_msgb2, g_msgb2);
    cudaGetSymbolAddress((void**)&p_inv,   g_invdeg);
    cudaGetSymbolAddress((void**)&p_cs,    g_colsum);
    cudaGetSymbolAddress((void**)&p_cnt,   g_cnt);
    cudaGetSymbolAddress((void**)&p_rank,  g_rank);
    cudaGetSymbolAddress((void**)&p_rp,    g_rowptr);
    cudaGetSymbolAddress((void**)&p_col,   g_col);
    cudaGetSymbolAddress((void**)&p_bsum,  g_bsum);
    cudaGetSymbolAddress((void**)&p_boff,  g_boff);

    const int gemm_blocks = (NN + 127) / 128;        // 391
    const int edge_blocks = (EE + 255) / 256;        // 3125
    const int node_blocks = NBLK;                    // 196
    const int gath_blocks = (NN * 32 + 255) / 256;   // 6250

    // side stream + fork/join events + smem opt-in (host objects, created once)
    static cudaStream_t s2 = nullptr;
    static cudaEvent_t evFork = nullptr, evJoin = nullptr;
    if (s2 == nullptr) {
        cudaStreamCreateWithFlags(&s2, cudaStreamNonBlocking);
        cudaEventCreateWithFlags(&evFork, cudaEventDisableTiming);
        cudaEventCreateWithFlags(&evJoin, cudaEventDisableTiming);
        cudaFuncSetAttribute(fused_layer<false>,
                             cudaFuncAttributeMaxDynamicSharedMemorySize, FUSED_SMEM_BYTES);
        cudaFuncSetAttribute(fused_layer<true>,
                             cudaFuncAttributeMaxDynamicSharedMemorySize, FUSED_SMEM_BYTES);
    }

    // 0) zero colsum on the MAIN stream (proj GEMM epilogue accumulates into it)
    zero_cs_kernel<<<2, 256>>>(p_cs);

    // ---- fork ----
    cudaEventRecord(evFork, 0);
    cudaStreamWaitEvent(s2, evFork, 0);

    // s2 leg: invdeg + CSR build
    init_kernel<<<node_blocks, 256, 0, s2>>>(degree, p_inv, p_cnt);
    hist_kernel<<<edge_blocks, 256, 0, s2>>>(dst, p_cnt, p_rank);
    scan1_kernel<<<node_blocks, 256, 0, s2>>>(p_cnt, p_rp, p_bsum);
    scan2_kernel<<<1, 256, 0, s2>>>(p_bsum, p_boff, p_rp);
    scan3_kernel<<<node_blocks, 256, 0, s2>>>(p_rp, p_boff);
    fill_kernel<<<edge_blocks, 256, 0, s2>>>(src, dst, p_rp, p_rank, p_col);
    cudaEventRecord(evJoin, s2);

    // main leg: projection GEMM: h0b = bf16(node_feat @ Wn + bn), colsum[0:128]
    gemm_proj<<<gemm_blocks, 256>>>(node_feat, Wn, bn, p_h0b, p_cs);

    // ---- join ----
    cudaStreamWaitEvent(0, evJoin, 0);

    // fusion: cur[v] = sum h0b[u]; msgb[v] = bf16(cur[v]*invdeg[v])
    fusion_gather_kernel<<<gath_blocks, 256>>>(p_h0b, p_cur, p_msgb, p_inv, p_rp, p_col);

    // 3 fused GCN layers (gather + GEMM in one kernel; ping-pong buffers)
    fused_layer<false><<<gemm_blocks, 512, FUSED_SMEM_BYTES>>>(
        p_cur, p_msgb, Wgcn, bgcn, p_cur2, p_msgb2, p_inv, p_rp, p_col, p_cs, 1 * HH);
    fused_layer<false><<<gemm_blocks, 512, FUSED_SMEM_BYTES>>>(
        p_cur2, p_msgb2, Wgcn, bgcn, p_cur, p_msgb, p_inv, p_rp, p_col, p_cs, 2 * HH);
    fused_layer<true><<<gemm_blocks, 512, FUSED_SMEM_BYTES>>>(
        p_cur, p_msgb, Wgcn, bgcn, nullptr, nullptr, p_inv, p_rp, p_col, p_cs, 3 * HH);

    // readout
    final_kernel<<<1, 128>>>(p_cs, Wpred, bpred, Wcls, bcls, out);
}

// round 13
// speedup vs baseline: 1.0640x; 1.0640x over previous
#include <cuda_runtime.h>
#include <cuda_bf16.h>
#include <cstddef>

#define NN 50000
#define EE 800000
#define NF 256
#define HH 128
#define LL 3
#define NEG_SLOPE 0.01f
#define NBLK 196   // ceil(NN/256)

// ---------------- scratch (no allocations allowed) ----------------
__device__ float         g_cur[(size_t)NN * HH];   // current hidden h (fp32)
__device__ float         g_agg[(size_t)NN * HH];   // aggregation buffer (fp32)
__device__ __nv_bfloat16 g_h0b[(size_t)NN * HH];   // projection output (bf16)
__device__ __nv_bfloat16 g_msgb[(size_t)NN * HH];  // h*invdeg messages (bf16)
__device__ float g_invdeg[NN];
__device__ float g_colsum[HH * (LL + 1)];
__device__ int   g_cnt[NN];
__device__ int   g_rank[EE];
__device__ int   g_rowptr[NN + 1];
__device__ int   g_col[EE];                // src node per dst-sorted edge
__device__ int   g_bsum[NBLK];
__device__ int   g_boff[NBLK];

// ---------------- helpers ----------------
__device__ __forceinline__ unsigned f2tf32(float x) {
    unsigned u;
    asm("cvt.rna.tf32.f32 %0, %1;" : "=r"(u) : "f"(x));
    return u;
}

__device__ __forceinline__ unsigned packbf2(float lo, float hi) {
    __nv_bfloat162 b = __floats2bfloat162_rn(lo, hi);
    return *reinterpret_cast<unsigned*>(&b);
}

__device__ __forceinline__ void mma_tf32(float* d, const unsigned* a, const unsigned* b) {
    asm volatile(
        "mma.sync.aligned.m16n8k8.row.col.f32.tf32.tf32.f32 "
        "{%0,%1,%2,%3}, {%4,%5,%6,%7}, {%8,%9}, {%0,%1,%2,%3};\n"
        : "+f"(d[0]), "+f"(d[1]), "+f"(d[2]), "+f"(d[3])
        : "r"(a[0]), "r"(a[1]), "r"(a[2]), "r"(a[3]), "r"(b[0]), "r"(b[1]));
}

__device__ __forceinline__ void acc_bf16row(float4& acc, const __nv_bfloat16* p) {
    uint2 r = *reinterpret_cast<const uint2*>(p);
    __nv_bfloat162 b0 = *reinterpret_cast<const __nv_bfloat162*>(&r.x);
    __nv_bfloat162 b1 = *reinterpret_cast<const __nv_bfloat162*>(&r.y);
    float2 f0 = __bfloat1622float2(b0);
    float2 f1 = __bfloat1622float2(b1);
    acc.x += f0.x; acc.y += f0.y; acc.z += f1.x; acc.w += f1.y;
}

// ---------------- colsum zero (main stream, before fork) ----------------
__global__ void zero_cs_kernel(float* __restrict__ cs) {
    int i = blockIdx.x * blockDim.x + threadIdx.x;
    if (i < HH * (LL + 1)) cs[i] = 0.f;
}

// ---------------- init (s2): counters + invdeg ----------------
__global__ void init_kernel(const float* __restrict__ degree, float* __restrict__ invdeg,
                            int* __restrict__ cnt) {
    int i = blockIdx.x * blockDim.x + threadIdx.x;
    if (i < NN) {
        invdeg[i] = 1.0f / degree[i];
        cnt[i] = 0;
    }
}

// ---------------- CSR build ----------------
__global__ void hist_kernel(const int* __restrict__ dst, int* __restrict__ cnt,
                            int* __restrict__ rank) {
    int e = blockIdx.x * blockDim.x + threadIdx.x;
    if (e < EE) rank[e] = atomicAdd(&cnt[dst[e]], 1);
}

__global__ void scan1_kernel(const int* __restrict__ cnt, int* __restrict__ rowptr,
                             int* __restrict__ bsum) {
    __shared__ int ws[8];
    int tid = threadIdx.x, lane = tid & 31, wid = tid >> 5;
    int i = blockIdx.x * 256 + tid;
    int v = (i < NN) ? cnt[i] : 0;
    int x = v;
#pragma unroll
    for (int off = 1; off < 32; off <<= 1) {
        int y = __shfl_up_sync(0xffffffffu, x, off);
        if (lane >= off) x += y;
    }
    if (lane == 31) ws[wid] = x;
    __syncthreads();
    if (wid == 0 && lane < 8) {
        int s = ws[lane];
#pragma unroll
        for (int off = 1; off < 8; off <<= 1) {
            int y = __shfl_up_sync(0x000000ffu, s, off);
            if (lane >= off) s += y;
        }
        ws[lane] = s;
    }
    __syncthreads();
    int woff = wid ? ws[wid - 1] : 0;
    if (i < NN) rowptr[i] = woff + x - v;
    if (tid == 255) bsum[blockIdx.x] = woff + x;
}

__global__ void scan2_kernel(const int* __restrict__ bsum, int* __restrict__ boff,
                             int* __restrict__ rowptr) {
    __shared__ int ws[8];
    int tid = threadIdx.x, lane = tid & 31, wid = tid >> 5;
    int v = (tid < NBLK) ? bsum[tid] : 0;
    int x = v;
#pragma unroll
    for (int off = 1; off < 32; off <<= 1) {
        int y = __shfl_up_sync(0xffffffffu, x, off);
        if (lane >= off) x += y;
    }
    if (lane == 31) ws[wid] = x;
    __syncthreads();
    if (wid == 0 && lane < 8) {
        int s = ws[lane];
#pragma unroll
        for (int off = 1; off < 8; off <<= 1) {
            int y = __shfl_up_sync(0x000000ffu, s, off);
            if (lane >= off) s += y;
        }
        ws[lane] = s;
    }
    __syncthreads();
    int woff = wid ? ws[wid - 1] : 0;
    if (tid < NBLK) boff[tid] = woff + x - v;
    if (tid == 255) rowptr[NN] = woff + x;
}

__global__ void scan3_kernel(int* __restrict__ rowptr, const int* __restrict__ boff) {
    int i = blockIdx.x * 256 + threadIdx.x;
    if (i < NN) rowptr[i] += boff[blockIdx.x];
}

__global__ void fill_kernel(const int* __restrict__ src, const int* __restrict__ dst,
                            const int* __restrict__ rowptr, const int* __restrict__ rank,
                            int* __restrict__ col) {
    int e = blockIdx.x * blockDim.x + threadIdx.x;
    if (e >= EE) return;
    col[rowptr[dst[e]] + rank[e]] = src[e];
}

// ---------------- gather (bf16 messages): out[v] = (base[v]?) + sum msg[u] -------------
// OUTB16: additionally write outb[v] = out[v]*invdeg[v] as bf16.
template <bool ADDBASE, bool OUTB16>
__global__ __launch_bounds__(256)
void gather_kernel(const __nv_bfloat16* __restrict__ msg, const float* __restrict__ base,
                   float* __restrict__ out, __nv_bfloat16* __restrict__ outb,
                   const float* __restrict__ invdeg,
                   const int* __restrict__ rowptr, const int* __restrict__ col) {
    int node = (blockIdx.x * blockDim.x + threadIdx.x) >> 5;
    int lane = threadIdx.x & 31;
    if (node >= NN) return;
    int s0 = __ldg(rowptr + node), s1 = __ldg(rowptr + node + 1);

    float4 acc;
    if (ADDBASE)
        acc = *reinterpret_cast<const float4*>(base + (size_t)node * HH + lane * 4);
    else
        acc = make_float4(0.f, 0.f, 0.f, 0.f);

    const __nv_bfloat16* mbase = msg + lane * 4;
    int e = s0;
    for (; e + 3 < s1; e += 4) {
        int u0 = __ldg(col + e),     u1 = __ldg(col + e + 1);
        int u2 = __ldg(col + e + 2), u3 = __ldg(col + e + 3);
        acc_bf16row(acc, mbase + (size_t)u0 * HH);
        acc_bf16row(acc, mbase + (size_t)u1 * HH);
        acc_bf16row(acc, mbase + (size_t)u2 * HH);
        acc_bf16row(acc, mbase + (size_t)u3 * HH);
    }
    for (; e < s1; e++) {
        int u0 = __ldg(col + e);
        acc_bf16row(acc, mbase + (size_t)u0 * HH);
    }

    *reinterpret_cast<float4*>(out + (size_t)node * HH + lane * 4) = acc;
    if (OUTB16) {
        float iv = __ldg(invdeg + node);
        uint2 p;
        p.x = packbf2(acc.x * iv, acc.y * iv);
        p.y = packbf2(acc.z * iv, acc.w * iv);
        *reinterpret_cast<uint2*>(outb + (size_t)node * HH + lane * 4) = p;
    }
}

// ---------------- tf32 tensor-core GEMM (double-buffered mainloop) ----------------
// OUTMODE: 0 = colsum only; 1 = bf16 unscaled to Cb; 2 = fp32 to C + bf16*invdeg to Cb.
template <int K, bool LEAKY, int OUTMODE>
__global__ __launch_bounds__(256, 2)
void gemm_tc(const float* __restrict__ A, const float* __restrict__ W,
             const float* __restrict__ bias, float* __restrict__ C,
             __nv_bfloat16* __restrict__ Cb, const float* __restrict__ invdeg,
             float* __restrict__ colsum, int cs_off) {
    __shared__ unsigned As[128][36];
    __shared__ unsigned Ws[32][132];
    __shared__ float colsm[HH];

    const int tid = threadIdx.x;
    const int warp = tid >> 5, lane = tid & 31;
    const int wm = warp & 3, wn = warp >> 2;
    const int g = lane >> 2, t = lane & 3;
    const int row0 = blockIdx.x * 128;

    // per-thread tile-load coordinates
    const int ar = tid >> 3, aq = tid & 7;       // A: rows ar, ar+? (4 frags of 1024)
    const int wk = tid >> 5, wn4 = tid & 31;     // W

    float acc[2][8][4];
#pragma unroll
    for (int mt = 0; mt < 2; mt++)
#pragma unroll
        for (int nt = 0; nt < 8; nt++)
#pragma unroll
            for (int r = 0; r < 4; r++) acc[mt][nt][r] = 0.f;

    if (tid < HH) colsm[tid] = 0.f;

    const int KT = K / 32;
    float4 av[4], wv[4];

    // prefetch tile 0
#pragma unroll
    for (int i = 0; i < 4; i++) {
        int idx = tid + i * 256;
        int r = idx >> 3, q = idx & 7;
        av[i] = make_float4(0.f, 0.f, 0.f, 0.f);
        if (row0 + r < NN)
            av[i] = *reinterpret_cast<const float4*>(A + (size_t)(row0 + r) * K + q * 4);
    }
#pragma unroll
    for (int i = 0; i < 4; i++) {
        int idx = tid + i * 256;
        int kk = idx >> 5, n4 = idx & 31;
        wv[i] = *reinterpret_cast<const float4*>(W + (size_t)kk * HH + n4 * 4);
    }

    for (int kt = 0; kt < KT; kt++) {
        // store current tile to smem (with tf32 cvt)
#pragma unroll
        for (int i = 0; i < 4; i++) {
            int idx = tid + i * 256;
            int r = idx >> 3, q = idx & 7;
            unsigned* p = &As[r][q * 4];
            p[0] = f2tf32(av[i].x); p[1] = f2tf32(av[i].y);
            p[2] = f2tf32(av[i].z); p[3] = f2tf32(av[i].w);
        }
#pragma unroll
        for (int i = 0; i < 4; i++) {
            int idx = tid + i * 256;
            int kk = idx >> 5, n4 = idx & 31;
            unsigned* p = &Ws[kk][n4 * 4];
            p[0] = f2tf32(wv[i].x); p[1] = f2tf32(wv[i].y);
            p[2] = f2tf32(wv[i].z); p[3] = f2tf32(wv[i].w);
        }
        __syncthreads();

        // prefetch next tile while MMAs run
        if (kt + 1 < KT) {
            const int k0 = (kt + 1) * 32;
#pragma unroll
            for (int i = 0; i < 4; i++) {
                int idx = tid + i * 256;
                int r = idx >> 3, q = idx & 7;
                av[i] = make_float4(0.f, 0.f, 0.f, 0.f);
                if (row0 + r < NN)
                    av[i] = *reinterpret_cast<const float4*>(
                        A + (size_t)(row0 + r) * K + k0 + q * 4);
            }
#pragma unroll
            for (int i = 0; i < 4; i++) {
                int idx = tid + i * 256;
                int kk = idx >> 5, n4 = idx & 31;
                wv[i] = *reinterpret_cast<const float4*>(
                    W + (size_t)(k0 + kk) * HH + n4 * 4);
            }
        }

#pragma unroll
        for (int k8 = 0; k8 < 4; k8++) {
            const int kk = k8 * 8;
            unsigned a[2][4], b[8][2];
#pragma unroll
            for (int mt = 0; mt < 2; mt++) {
                int r = wm * 32 + mt * 16;
                a[mt][0] = As[r + g][kk + t];
                a[mt][1] = As[r + g + 8][kk + t];
                a[mt][2] = As[r + g][kk + t + 4];
                a[mt][3] = As[r + g + 8][kk + t + 4];
            }
#pragma unroll
            for (int nt = 0; nt < 8; nt++) {
                int n = wn * 64 + nt * 8;
                b[nt][0] = Ws[kk + t][n + g];
                b[nt][1] = Ws[kk + t + 4][n + g];
            }
#pragma unroll
            for (int mt = 0; mt < 2; mt++)
#pragma unroll
                for (int nt = 0; nt < 8; nt++)
                    mma_tf32(acc[mt][nt], a[mt], b[nt]);
        }
        __syncthreads();
    }

    float csum[8][2];
#pragma unroll
    for (int nt = 0; nt < 8; nt++) { csum[nt][0] = 0.f; csum[nt][1] = 0.f; }

#pragma unroll
    for (int mt = 0; mt < 2; mt++) {
        int rr[2];
        rr[0] = row0 + wm * 32 + mt * 16 + g;
        rr[1] = rr[0] + 8;
#pragma unroll
        for (int half = 0; half < 2; half++) {
            int r = rr[half];
            if (r >= NN) continue;
            float iv = (OUTMODE == 2) ? __ldg(invdeg + r) : 1.0f;
#pragma unroll
            for (int nt = 0; nt < 8; nt++) {
                int col = wn * 64 + nt * 8 + 2 * t;
                float b0 = __ldg(bias + col), b1 = __ldg(bias + col + 1);
                float x0 = acc[mt][nt][half * 2 + 0] + b0;
                float x1 = acc[mt][nt][half * 2 + 1] + b1;
                if (LEAKY) {
                    x0 = (x0 >= 0.f) ? x0 : NEG_SLOPE * x0;
                    x1 = (x1 >= 0.f) ? x1 : NEG_SLOPE * x1;
                }
                csum[nt][0] += x0; csum[nt][1] += x1;
                if (OUTMODE == 2)
                    *reinterpret_cast<float2*>(C + (size_t)r * HH + col) = make_float2(x0, x1);
                if (OUTMODE == 1 || OUTMODE == 2) {
                    *reinterpret_cast<unsigned*>(Cb + (size_t)r * HH + col) =
                        packbf2(x0 * iv, x1 * iv);
                }
            }
        }
    }

    __syncthreads();
#pragma unroll
    for (int nt = 0; nt < 8; nt++) {
#pragma unroll
        for (int c = 0; c < 2; c++) {
            float s = csum[nt][c];
            s += __shfl_xor_sync(0xffffffffu, s, 4);
            s += __shfl_xor_sync(0xffffffffu, s, 8);
            s += __shfl_xor_sync(0xffffffffu, s, 16);
            if (g == 0) atomicAdd(&colsm[wn * 64 + nt * 8 + 2 * t + c], s);
        }
    }
    __syncthreads();
    if (tid < HH) atomicAdd(&colsum[cs_off + tid], colsm[tid]);
}

// ---------------- final ----------------
__global__ void final_kernel(const float* __restrict__ colsum,
                             const float* __restrict__ Wpred, const float* __restrict__ bpred,
                             const float* __restrict__ Wcls, const float* __restrict__ bcls,
                             float* __restrict__ out) {
    __shared__ float cm[HH * (LL + 1)];
    __shared__ float gsh[HH];
    int tid = threadIdx.x;  // 128 threads
    for (int t = tid; t < HH * (LL + 1); t += 128) cm[t] = colsum[t] * (1.0f / (float)NN);
    __syncthreads();
    float g = bpred[tid];
    for (int k = 0; k < HH * (LL + 1); k++) g += cm[k] * Wpred[(size_t)k * HH + tid];
    gsh[tid] = g;
    __syncthreads();
    if (tid == 0) {
        float l0 = bcls[0], l1 = bcls[1];
        for (int j = 0; j < HH; j++) {
            l0 += gsh[j] * Wcls[j * 2 + 0];
            l1 += gsh[j] * Wcls[j * 2 + 1];
        }
        float m = fmaxf(l0, l1);
        float e0 = expf(l0 - m), e1 = expf(l1 - m);
        float inv = 1.0f / (e0 + e1);
        out[0] = e0 * inv;
        out[1] = e1 * inv;
    }
}

// ---------------- launch ----------------
extern "C" void kernel_launch(void* const* d_in, const int* in_sizes, int n_in,
                              void* d_out, int out_size) {
    const float* node_feat = (const float*)d_in[0];
    const float* degree    = (const float*)d_in[3];
    const float* Wn        = (const float*)d_in[4];
    const float* bn        = (const float*)d_in[5];
    const float* Wgcn      = (const float*)d_in[8];
    const float* bgcn      = (const float*)d_in[9];
    const float* Wpred     = (const float*)d_in[10];
    const float* bpred     = (const float*)d_in[11];
    const float* Wcls      = (const float*)d_in[12];
    const float* bcls      = (const float*)d_in[13];
    const int*   src       = (const int*)d_in[14];
    const int*   dst       = (const int*)d_in[15];
    float* out = (float*)d_out;

    float *p_cur, *p_agg, *p_inv, *p_cs;
    __nv_bfloat16 *p_h0b, *p_msgb;
    int *p_cnt, *p_rank, *p_rp, *p_col, *p_bsum, *p_boff;
    cudaGetSymbolAddress((void**)&p_cur,  g_cur);
    cudaGetSymbolAddress((void**)&p_agg,  g_agg);
    cudaGetSymbolAddress((void**)&p_h0b,  g_h0b);
    cudaGetSymbolAddress((void**)&p_msgb, g_msgb);
    cudaGetSymbolAddress((void**)&p_inv,  g_invdeg);
    cudaGetSymbolAddress((void**)&p_cs,   g_colsum);
    cudaGetSymbolAddress((void**)&p_cnt,  g_cnt);
    cudaGetSymbolAddress((void**)&p_rank, g_rank);
    cudaGetSymbolAddress((void**)&p_rp,   g_rowptr);
    cudaGetSymbolAddress((void**)&p_col,  g_col);
    cudaGetSymbolAddress((void**)&p_bsum, g_bsum);
    cudaGetSymbolAddress((void**)&p_boff, g_boff);

    const int gemm_blocks = (NN + 127) / 128;        // 391
    const int edge_blocks = (EE + 255) / 256;        // 3125
    const int node_blocks = NBLK;                    // 196
    const int gath_blocks = (NN * 32 + 255) / 256;   // 6250

    // side stream + fork/join events (host objects, created once; no device alloc)
    static cudaStream_t s2 = nullptr;
    static cudaEvent_t evFork = nullptr, evJoin = nullptr;
    if (s2 == nullptr) {
        cudaStreamCreateWithFlags(&s2, cudaStreamNonBlocking);
        cudaEventCreateWithFlags(&evFork, cudaEventDisableTiming);
        cudaEventCreateWithFlags(&evJoin, cudaEventDisableTiming);
    }

    // 0) zero colsum on the MAIN stream (proj GEMM epilogue accumulates into it)
    zero_cs_kernel<<<2, 256>>>(p_cs);

    // ---- fork ----
    cudaEventRecord(evFork, 0);
    cudaStreamWaitEvent(s2, evFork, 0);

    // s2 leg: invdeg + CSR build
    init_kernel<<<node_blocks, 256, 0, s2>>>(degree, p_inv, p_cnt);
    hist_kernel<<<edge_blocks, 256, 0, s2>>>(dst, p_cnt, p_rank);
    scan1_kernel<<<node_blocks, 256, 0, s2>>>(p_cnt, p_rp, p_bsum);
    scan2_kernel<<<1, 256, 0, s2>>>(p_bsum, p_boff, p_rp);
    scan3_kernel<<<node_blocks, 256, 0, s2>>>(p_rp, p_boff);
    fill_kernel<<<edge_blocks, 256, 0, s2>>>(src, dst, p_rp, p_rank, p_col);
    cudaEventRecord(evJoin, s2);

    // main leg: projection GEMM (independent of CSR): h0b = bf16(A@Wn+bn), colsum[0:128]
    gemm_tc<NF, false, 1><<<gemm_blocks, 256>>>(node_feat, Wn, bn, nullptr, p_h0b,
                                                nullptr, p_cs, 0);

    // ---- join: fusion gather needs CSR + invdeg (s2) and h0b (main) ----
    cudaStreamWaitEvent(0, evJoin, 0);

    // fusion: cur[v] = sum_{u->v} h0b[u] ; msgb[v] = bf16(cur[v]*invdeg[v])
    gather_kernel<false, true><<<gath_blocks, 256>>>(p_h0b, nullptr, p_cur, p_msgb,
                                                     p_inv, p_rp, p_col);

    // 3 GCN layers
    for (int l = 0; l < LL; l++) {
        gather_kernel<true, false><<<gath_blocks, 256>>>(p_msgb, p_cur, p_agg, nullptr,
                                                         nullptr, p_rp, p_col);
        if (l < LL - 1)
            gemm_tc<HH, true, 2><<<gemm_blocks, 256>>>(p_agg, Wgcn, bgcn, p_cur, p_msgb,
                                                       p_inv, p_cs, (l + 1) * HH);
        else
            gemm_tc<HH, true, 0><<<gemm_blocks, 256>>>(p_agg, Wgcn, bgcn, nullptr, nullptr,
                                                       nullptr, p_cs, (l + 1) * HH);
    }

    // readout
    final_kernel<<<1, 128>>>(p_cs, Wpred, bpred, Wcls, bcls, out);
}

// round 15
// speedup vs baseline: 1.2409x; 1.1662x over previous
#include <cuda_runtime.h>
#include <cuda_bf16.h>
#include <cstddef>

#define NN 50000
#define EE 800000
#define NF 256
#define HH 128
#define LL 3
#define NEG_SLOPE 0.01f
#define NBLK 196   // ceil(NN/256)

// GEMM smem: 2 stages of (As 128x36 + Ws 32x132) + colsm[128]
#define STG_WORDS (128 * 36 + 32 * 132)          // 8832
#define SMEM_GEMM_BYTES ((2 * STG_WORDS + HH) * 4)  // 71168

// ---------------- scratch (no allocations allowed) ----------------
__device__ float         g_cur[(size_t)NN * HH];   // current hidden h (fp32)
__device__ float         g_agg[(size_t)NN * HH];   // aggregation buffer (fp32)
__device__ __nv_bfloat16 g_h0b[(size_t)NN * HH];   // projection output (bf16)
__device__ __nv_bfloat16 g_msgb[(size_t)NN * HH];  // h*invdeg messages (bf16)
__device__ float g_invdeg[NN];
__device__ float g_colsum[HH * (LL + 1)];
__device__ int   g_cnt[NN];
__device__ int   g_rank[EE];
__device__ int   g_rowptr[NN + 1];
__device__ int   g_col[EE];                // src node per dst-sorted edge
__device__ int   g_bsum[NBLK];
__device__ int   g_boff[NBLK];

// ---------------- helpers ----------------
__device__ __forceinline__ unsigned packbf2(float lo, float hi) {
    __nv_bfloat162 b = __floats2bfloat162_rn(lo, hi);
    return *reinterpret_cast<unsigned*>(&b);
}

__device__ __forceinline__ void mma_tf32(float* d, const unsigned* a, const unsigned* b) {
    asm volatile(
        "mma.sync.aligned.m16n8k8.row.col.f32.tf32.tf32.f32 "
        "{%0,%1,%2,%3}, {%4,%5,%6,%7}, {%8,%9}, {%0,%1,%2,%3};\n"
        : "+f"(d[0]), "+f"(d[1]), "+f"(d[2]), "+f"(d[3])
        : "r"(a[0]), "r"(a[1]), "r"(a[2]), "r"(a[3]), "r"(b[0]), "r"(b[1]));
}

__device__ __forceinline__ void acc_bf16row(float4& acc, const __nv_bfloat16* p) {
    uint2 r = *reinterpret_cast<const uint2*>(p);
    __nv_bfloat162 b0 = *reinterpret_cast<const __nv_bfloat162*>(&r.x);
    __nv_bfloat162 b1 = *reinterpret_cast<const __nv_bfloat162*>(&r.y);
    float2 f0 = __bfloat1622float2(b0);
    float2 f1 = __bfloat1622float2(b1);
    acc.x += f0.x; acc.y += f0.y; acc.z += f1.x; acc.w += f1.y;
}

// cp.async 16B with zero-fill when src_bytes < 16
__device__ __forceinline__ void cp_async16(void* smem_dst, const void* gsrc, int src_bytes) {
    unsigned s = (unsigned)__cvta_generic_to_shared(smem_dst);
    asm volatile("cp.async.ca.shared.global [%0], [%1], 16, %2;\n"
                 :: "r"(s), "l"(gsrc), "r"(src_bytes) : "memory");
}
__device__ __forceinline__ void cp_commit() {
    asm volatile("cp.async.commit_group;\n" ::: "memory");
}
template <int N>
__device__ __forceinline__ void cp_wait() {
    asm volatile("cp.async.wait_group %0;\n" :: "n"(N) : "memory");
}

// ---------------- colsum zero (main stream, before fork) ----------------
__global__ void zero_cs_kernel(float* __restrict__ cs) {
    int i = blockIdx.x * blockDim.x + threadIdx.x;
    if (i < HH * (LL + 1)) cs[i] = 0.f;
}

// ---------------- init (s2): counters + invdeg ----------------
__global__ void init_kernel(const float* __restrict__ degree, float* __restrict__ invdeg,
                            int* __restrict__ cnt) {
    int i = blockIdx.x * blockDim.x + threadIdx.x;
    if (i < NN) {
        invdeg[i] = 1.0f / degree[i];
        cnt[i] = 0;
    }
}

// ---------------- CSR build ----------------
__global__ void hist_kernel(const int* __restrict__ dst, int* __restrict__ cnt,
                            int* __restrict__ rank) {
    int e = blockIdx.x * blockDim.x + threadIdx.x;
    if (e < EE) rank[e] = atomicAdd(&cnt[dst[e]], 1);
}

__global__ void scan1_kernel(const int* __restrict__ cnt, int* __restrict__ rowptr,
                             int* __restrict__ bsum) {
    __shared__ int ws[8];
    int tid = threadIdx.x, lane = tid & 31, wid = tid >> 5;
    int i = blockIdx.x * 256 + tid;
    int v = (i < NN) ? cnt[i] : 0;
    int x = v;
#pragma unroll
    for (int off = 1; off < 32; off <<= 1) {
        int y = __shfl_up_sync(0xffffffffu, x, off);
        if (lane >= off) x += y;
    }
    if (lane == 31) ws[wid] = x;
    __syncthreads();
    if (wid == 0 && lane < 8) {
        int s = ws[lane];
#pragma unroll
        for (int off = 1; off < 8; off <<= 1) {
            int y = __shfl_up_sync(0x000000ffu, s, off);
            if (lane >= off) s += y;
        }
        ws[lane] = s;
    }
    __syncthreads();
    int woff = wid ? ws[wid - 1] : 0;
    if (i < NN) rowptr[i] = woff + x - v;
    if (tid == 255) bsum[blockIdx.x] = woff + x;
}

__global__ void scan2_kernel(const int* __restrict__ bsum, int* __restrict__ boff,
                             int* __restrict__ rowptr) {
    __shared__ int ws[8];
    int tid = threadIdx.x, lane = tid & 31, wid = tid >> 5;
    int v = (tid < NBLK) ? bsum[tid] : 0;
    int x = v;
#pragma unroll
    for (int off = 1; off < 32; off <<= 1) {
        int y = __shfl_up_sync(0xffffffffu, x, off);
        if (lane >= off) x += y;
    }
    if (lane == 31) ws[wid] = x;
    __syncthreads();
    if (wid == 0 && lane < 8) {
        int s = ws[lane];
#pragma unroll
        for (int off = 1; off < 8; off <<= 1) {
            int y = __shfl_up_sync(0x000000ffu, s, off);
            if (lane >= off) s += y;
        }
        ws[lane] = s;
    }
    __syncthreads();
    int woff = wid ? ws[wid - 1] : 0;
    if (tid < NBLK) boff[tid] = woff + x - v;
    if (tid == 255) rowptr[NN] = woff + x;
}

__global__ void scan3_kernel(int* __restrict__ rowptr, const int* __restrict__ boff) {
    int i = blockIdx.x * 256 + threadIdx.x;
    if (i < NN) rowptr[i] += boff[blockIdx.x];
}

__global__ void fill_kernel(const int* __restrict__ src, const int* __restrict__ dst,
                            const int* __restrict__ rowptr, const int* __restrict__ rank,
                            int* __restrict__ col) {
    int e = blockIdx.x * blockDim.x + threadIdx.x;
    if (e >= EE) return;
    col[rowptr[dst[e]] + rank[e]] = src[e];
}

// ---------------- gather (bf16 messages): out[v] = (base[v]?) + sum msg[u] -------------
template <bool ADDBASE, bool OUTB16>
__global__ __launch_bounds__(256)
void gather_kernel(const __nv_bfloat16* __restrict__ msg, const float* __restrict__ base,
                   float* __restrict__ out, __nv_bfloat16* __restrict__ outb,
                   const float* __restrict__ invdeg,
                   const int* __restrict__ rowptr, const int* __restrict__ col) {
    int node = (blockIdx.x * blockDim.x + threadIdx.x) >> 5;
    int lane = threadIdx.x & 31;
    if (node >= NN) return;
    int s0 = __ldg(rowptr + node), s1 = __ldg(rowptr + node + 1);

    float4 acc;
    if (ADDBASE)
        acc = *reinterpret_cast<const float4*>(base + (size_t)node * HH + lane * 4);
    else
        acc = make_float4(0.f, 0.f, 0.f, 0.f);

    const __nv_bfloat16* mbase = msg + lane * 4;
    int e = s0;
    for (; e + 3 < s1; e += 4) {
        int u0 = __ldg(col + e),     u1 = __ldg(col + e + 1);
        int u2 = __ldg(col + e + 2), u3 = __ldg(col + e + 3);
        acc_bf16row(acc, mbase + (size_t)u0 * HH);
        acc_bf16row(acc, mbase + (size_t)u1 * HH);
        acc_bf16row(acc, mbase + (size_t)u2 * HH);
        acc_bf16row(acc, mbase + (size_t)u3 * HH);
    }
    for (; e < s1; e++) {
        int u0 = __ldg(col + e);
        acc_bf16row(acc, mbase + (size_t)u0 * HH);
    }

    *reinterpret_cast<float4*>(out + (size_t)node * HH + lane * 4) = acc;
    if (OUTB16) {
        float iv = __ldg(invdeg + node);
        uint2 p;
        p.x = packbf2(acc.x * iv, acc.y * iv);
        p.y = packbf2(acc.z * iv, acc.w * iv);
        *reinterpret_cast<uint2*>(outb + (size_t)node * HH + lane * 4) = p;
    }
}

// ---------------- tf32 tensor-core GEMM (cp.async 2-stage pipeline) ----------------
// OUTMODE: 0 = colsum only; 1 = bf16 unscaled to Cb; 2 = fp32 to C + bf16*invdeg to Cb.
template <int K, bool LEAKY, int OUTMODE>
__global__ __launch_bounds__(256, 2)
void gemm_tc(const float* __restrict__ A, const float* __restrict__ W,
             const float* __restrict__ bias, float* __restrict__ C,
             __nv_bfloat16* __restrict__ Cb, const float* __restrict__ invdeg,
             float* __restrict__ colsum, int cs_off) {
    extern __shared__ unsigned smem[];
    float* colsm = reinterpret_cast<float*>(smem + 2 * STG_WORDS);

    const int tid = threadIdx.x;
    const int warp = tid >> 5, lane = tid & 31;
    const int wm = warp & 3, wn = warp >> 2;
    const int g = lane >> 2, t = lane & 3;
    const int row0 = blockIdx.x * 128;
    const int KT = K / 32;

    float acc[2][8][4];
#pragma unroll
    for (int mt = 0; mt < 2; mt++)
#pragma unroll
        for (int nt = 0; nt < 8; nt++)
#pragma unroll
            for (int r = 0; r < 4; r++) acc[mt][nt][r] = 0.f;

    if (tid < HH) colsm[tid] = 0.f;

    // tile loader: issue cp.async for tile kt into stage s, then commit
    auto load_tile = [&](int kt, int s) {
        unsigned* AsS = smem + s * STG_WORDS;                 // [128][36]
        unsigned* WsS = smem + s * STG_WORDS + 128 * 36;      // [32][132]
        const int k0 = kt * 32;
#pragma unroll
        for (int i = 0; i < 4; i++) {
            int idx = tid + i * 256;
            int r = idx >> 3, q = idx & 7;
            const float* gs = A + (size_t)(row0 + r) * K + k0 + q * 4;
            cp_async16(AsS + r * 36 + q * 4, gs, (row0 + r < NN) ? 16 : 0);
        }
#pragma unroll
        for (int i = 0; i < 4; i++) {
            int idx = tid + i * 256;
            int kk = idx >> 5, n4 = idx & 31;
            const float* gs = W + (size_t)(k0 + kk) * HH + n4 * 4;
            cp_async16(WsS + kk * 132 + n4 * 4, gs, 16);
        }
        cp_commit();
    };

    load_tile(0, 0);

    for (int kt = 0; kt < KT; kt++) {
        const int s = kt & 1;
        if (kt + 1 < KT) {
            load_tile(kt + 1, s ^ 1);
            cp_wait<1>();   // tile kt complete, tile kt+1 in flight
        } else {
            cp_wait<0>();
        }
        __syncthreads();

        const unsigned* AsS = smem + s * STG_WORDS;
        const unsigned* WsS = smem + s * STG_WORDS + 128 * 36;

#pragma unroll
        for (int k8 = 0; k8 < 4; k8++) {
            const int kk = k8 * 8;
            unsigned a[2][4], b[8][2];
#pragma unroll
            for (int mt = 0; mt < 2; mt++) {
                int r = wm * 32 + mt * 16;
                a[mt][0] = AsS[(r + g) * 36 + kk + t];
                a[mt][1] = AsS[(r + g + 8) * 36 + kk + t];
                a[mt][2] = AsS[(r + g) * 36 + kk + t + 4];
                a[mt][3] = AsS[(r + g + 8) * 36 + kk + t + 4];
            }
#pragma unroll
            for (int nt = 0; nt < 8; nt++) {
                int n = wn * 64 + nt * 8;
                b[nt][0] = WsS[(kk + t) * 132 + n + g];
                b[nt][1] = WsS[(kk + t + 4) * 132 + n + g];
            }
#pragma unroll
            for (int mt = 0; mt < 2; mt++)
#pragma unroll
                for (int nt = 0; nt < 8; nt++)
                    mma_tf32(acc[mt][nt], a[mt], b[nt]);
        }
        __syncthreads();   // all reads of stage s done before it is refilled
    }

    float csum[8][2];
#pragma unroll
    for (int nt = 0; nt < 8; nt++) { csum[nt][0] = 0.f; csum[nt][1] = 0.f; }

#pragma unroll
    for (int mt = 0; mt < 2; mt++) {
        int rr[2];
        rr[0] = row0 + wm * 32 + mt * 16 + g;
        rr[1] = rr[0] + 8;
#pragma unroll
        for (int half = 0; half < 2; half++) {
            int r = rr[half];
            if (r >= NN) continue;
            float iv = (OUTMODE == 2) ? __ldg(invdeg + r) : 1.0f;
#pragma unroll
            for (int nt = 0; nt < 8; nt++) {
                int col = wn * 64 + nt * 8 + 2 * t;
                float b0 = __ldg(bias + col), b1 = __ldg(bias + col + 1);
                float x0 = acc[mt][nt][half * 2 + 0] + b0;
                float x1 = acc[mt][nt][half * 2 + 1] + b1;
                if (LEAKY) {
                    x0 = (x0 >= 0.f) ? x0 : NEG_SLOPE * x0;
                    x1 = (x1 >= 0.f) ? x1 : NEG_SLOPE * x1;
                }
                csum[nt][0] += x0; csum[nt][1] += x1;
                if (OUTMODE == 2)
                    *reinterpret_cast<float2*>(C + (size_t)r * HH + col) = make_float2(x0, x1);
                if (OUTMODE == 1 || OUTMODE == 2) {
                    *reinterpret_cast<unsigned*>(Cb + (size_t)r * HH + col) =
                        packbf2(x0 * iv, x1 * iv);
                }
            }
        }
    }

    __syncthreads();
#pragma unroll
    for (int nt = 0; nt < 8; nt++) {
#pragma unroll
        for (int c = 0; c < 2; c++) {
            float s = csum[nt][c];
            s += __shfl_xor_sync(0xffffffffu, s, 4);
            s += __shfl_xor_sync(0xffffffffu, s, 8);
            s += __shfl_xor_sync(0xffffffffu, s, 16);
            if (g == 0) atomicAdd(&colsm[wn * 64 + nt * 8 + 2 * t + c], s);
        }
    }
    __syncthreads();
    if (tid < HH) atomicAdd(&colsum[cs_off + tid], colsm[tid]);
}

// ---------------- final ----------------
__global__ void final_kernel(const float* __restrict__ colsum,
                             const float* __restrict__ Wpred, const float* __restrict__ bpred,
                             const float* __restrict__ Wcls, const float* __restrict__ bcls,
                             float* __restrict__ out) {
    __shared__ float cm[HH * (LL + 1)];
    __shared__ float gsh[HH];
    int tid = threadIdx.x;  // 128 threads
    for (int t = tid; t < HH * (LL + 1); t += 128) cm[t] = colsum[t] * (1.0f / (float)NN);
    __syncthreads();
    float g = bpred[tid];
    for (int k = 0; k < HH * (LL + 1); k++) g += cm[k] * Wpred[(size_t)k * HH + tid];
    gsh[tid] = g;
    __syncthreads();
    if (tid == 0) {
        float l0 = bcls[0], l1 = bcls[1];
        for (int j = 0; j < HH; j++) {
            l0 += gsh[j] * Wcls[j * 2 + 0];
            l1 += gsh[j] * Wcls[j * 2 + 1];
        }
        float m = fmaxf(l0, l1);
        float e0 = expf(l0 - m), e1 = expf(l1 - m);
        float inv = 1.0f / (e0 + e1);
        out[0] = e0 * inv;
        out[1] = e1 * inv;
    }
}

// ---------------- launch ----------------
extern "C" void kernel_launch(void* const* d_in, const int* in_sizes, int n_in,
                              void* d_out, int out_size) {
    const float* node_feat = (const float*)d_in[0];
    const float* degree    = (const float*)d_in[3];
    const float* Wn        = (const float*)d_in[4];
    const float* bn        = (const float*)d_in[5];
    const float* Wgcn      = (const float*)d_in[8];
    const float* bgcn      = (const float*)d_in[9];
    const float* Wpred     = (const float*)d_in[10];
    const float* bpred     = (const float*)d_in[11];
    const float* Wcls      = (const float*)d_in[12];
    const float* bcls      = (const float*)d_in[13];
    const int*   src       = (const int*)d_in[14];
    const int*   dst       = (const int*)d_in[15];
    float* out = (float*)d_out;

    float *p_cur, *p_agg, *p_inv, *p_cs;
    __nv_bfloat16 *p_h0b, *p_msgb;
    int *p_cnt, *p_rank, *p_rp, *p_col, *p_bsum, *p_boff;
    cudaGetSymbolAddress((void**)&p_cur,  g_cur);
    cudaGetSymbolAddress((void**)&p_agg,  g_agg);
    cudaGetSymbolAddress((void**)&p_h0b,  g_h0b);
    cudaGetSymbolAddress((void**)&p_msgb, g_msgb);
    cudaGetSymbolAddress((void**)&p_inv,  g_invdeg);
    cudaGetSymbolAddress((void**)&p_cs,   g_colsum);
    cudaGetSymbolAddress((void**)&p_cnt,  g_cnt);
    cudaGetSymbolAddress((void**)&p_rank, g_rank);
    cudaGetSymbolAddress((void**)&p_rp,   g_rowptr);
    cudaGetSymbolAddress((void**)&p_col,  g_col);
    cudaGetSymbolAddress((void**)&p_bsum, g_bsum);
    cudaGetSymbolAddress((void**)&p_boff, g_boff);

    const int gemm_blocks = (NN + 127) / 128;        // 391
    const int edge_blocks = (EE + 255) / 256;        // 3125
    const int node_blocks = NBLK;                    // 196
    const int gath_blocks = (NN * 32 + 255) / 256;   // 6250

    // side stream + fork/join events + smem opt-in (host objects, created once)
    static cudaStream_t s2 = nullptr;
    static cudaEvent_t evFork = nullptr, evJoin = nullptr;
    if (s2 == nullptr) {
        cudaStreamCreateWithFlags(&s2, cudaStreamNonBlocking);
        cudaEventCreateWithFlags(&evFork, cudaEventDisableTiming);
        cudaEventCreateWithFlags(&evJoin, cudaEventDisableTiming);
        cudaFuncSetAttribute(gemm_tc<NF, false, 1>,
                             cudaFuncAttributeMaxDynamicSharedMemorySize, SMEM_GEMM_BYTES);
        cudaFuncSetAttribute(gemm_tc<HH, true, 2>,
                             cudaFuncAttributeMaxDynamicSharedMemorySize, SMEM_GEMM_BYTES);
        cudaFuncSetAttribute(gemm_tc<HH, true, 0>,
                             cudaFuncAttributeMaxDynamicSharedMemorySize, SMEM_GEMM_BYTES);
    }

    // 0) zero colsum on the MAIN stream (proj GEMM epilogue accumulates into it)
    zero_cs_kernel<<<2, 256>>>(p_cs);

    // ---- fork ----
    cudaEventRecord(evFork, 0);
    cudaStreamWaitEvent(s2, evFork, 0);

    // s2 leg: invdeg + CSR build
    init_kernel<<<node_blocks, 256, 0, s2>>>(degree, p_inv, p_cnt);
    hist_kernel<<<edge_blocks, 256, 0, s2>>>(dst, p_cnt, p_rank);
    scan1_kernel<<<node_blocks, 256, 0, s2>>>(p_cnt, p_rp, p_bsum);
    scan2_kernel<<<1, 256, 0, s2>>>(p_bsum, p_boff, p_rp);
    scan3_kernel<<<node_blocks, 256, 0, s2>>>(p_rp, p_boff);
    fill_kernel<<<edge_blocks, 256, 0, s2>>>(src, dst, p_rp, p_rank, p_col);
    cudaEventRecord(evJoin, s2);

    // main leg: projection GEMM (independent of CSR): h0b = bf16(A@Wn+bn), colsum[0:128]
    gemm_tc<NF, false, 1><<<gemm_blocks, 256, SMEM_GEMM_BYTES>>>(
        node_feat, Wn, bn, nullptr, p_h0b, nullptr, p_cs, 0);

    // ---- join: fusion gather needs CSR + invdeg (s2) and h0b (main) ----
    cudaStreamWaitEvent(0, evJoin, 0);

    // fusion: cur[v] = sum_{u->v} h0b[u] ; msgb[v] = bf16(cur[v]*invdeg[v])
    gather_kernel<false, true><<<gath_blocks, 256>>>(p_h0b, nullptr, p_cur, p_msgb,
                                                     p_inv, p_rp, p_col);

    // 3 GCN layers
    for (int l = 0; l < LL; l++) {
        gather_kernel<true, false><<<gath_blocks, 256>>>(p_msgb, p_cur, p_agg, nullptr,
                                                         nullptr, p_rp, p_col);
        if (l < LL - 1)
            gemm_tc<HH, true, 2><<<gemm_blocks, 256, SMEM_GEMM_BYTES>>>(
                p_agg, Wgcn, bgcn, p_cur, p_msgb, p_inv, p_cs, (l + 1) * HH);
        else
            gemm_tc<HH, true, 0><<<gemm_blocks, 256, SMEM_GEMM_BYTES>>>(
                p_agg, Wgcn, bgcn, nullptr, nullptr, nullptr, p_cs, (l + 1) * HH);
    }

    // readout
    final_kernel<<<1, 128>>>(p_cs, Wpred, bpred, Wcls, bcls, out);
}